// round 2
// baseline (speedup 1.0000x reference)
#include <cuda_runtime.h>
#include <cstddef>

#define S_LEN 2048
#define BATCH 4
#define DIM   1024
#define MQKV  (BATCH * S_LEN)   // 8192

// ---- scratch (static device globals; no allocation in kernel_launch) ----
__device__ float g_xf[(size_t)MQKV * DIM];          // x transposed to (B,S,D)
__device__ float g_q [(size_t)MQKV * DIM];
__device__ float g_k [(size_t)MQKV * DIM];
__device__ float g_v [(size_t)MQKV * DIM];
__device__ float g_sc[(size_t)BATCH * S_LEN * S_LEN]; // scores / attn probs

// ---------------------------------------------------------------------------
// transpose: xf[(b*S+s)*D + d] = x[(s*B+b)*D + d]
// grid = B*S blocks, 256 threads, one float4 per thread (D/4 = 256)
// ---------------------------------------------------------------------------
__global__ __launch_bounds__(256) void transpose_x(const float* __restrict__ x,
                                                   float* __restrict__ xf) {
    int bs = blockIdx.x;
    int b = bs / S_LEN, s = bs % S_LEN;
    const float4* src = (const float4*)(x + ((size_t)s * BATCH + b) * DIM);
    float4* dst = (float4*)(xf + (size_t)bs * DIM);
    dst[threadIdx.x] = src[threadIdx.x];
}

// ---------------------------------------------------------------------------
// NT GEMM: C[m,n] = alpha * sum_k A[m,k] * Bw[n,k] (+ bias[n])
// A: M x K row-major, Bw: N x K row-major (both K-contiguous).
// Tile 128x128x16, 256 threads, 8x8 microtile. Batched via blockIdx.z strides.
// ---------------------------------------------------------------------------
__global__ __launch_bounds__(256, 2)
void gemm_nt(const float* __restrict__ A, const float* __restrict__ Bw,
             const float* __restrict__ bias, float* __restrict__ C,
             int M, int N, int K, float alpha,
             size_t sA, size_t sB, size_t sC)
{
    A  += sA * (size_t)blockIdx.z;
    Bw += sB * (size_t)blockIdx.z;
    C  += sC * (size_t)blockIdx.z;

    const int m0 = blockIdx.y * 128;
    const int n0 = blockIdx.x * 128;

    __shared__ float As[16][132];   // padded to dodge transpose-store conflicts
    __shared__ float Bs[16][132];

    const int tid = threadIdx.x;
    const int tx = tid & 15, ty = tid >> 4;
    const int lr = tid >> 2;          // 0..63
    const int lc = (tid & 3) << 2;    // 0,4,8,12

    float acc[8][8];
    #pragma unroll
    for (int i = 0; i < 8; ++i)
        #pragma unroll
        for (int j = 0; j < 8; ++j) acc[i][j] = 0.f;

    for (int k0 = 0; k0 < K; k0 += 16) {
        #pragma unroll
        for (int h = 0; h < 2; ++h) {
            int r = lr + h * 64;
            float4 va = *(const float4*)(A  + (size_t)(m0 + r) * K + k0 + lc);
            As[lc+0][r] = va.x; As[lc+1][r] = va.y;
            As[lc+2][r] = va.z; As[lc+3][r] = va.w;
            float4 vb = *(const float4*)(Bw + (size_t)(n0 + r) * K + k0 + lc);
            Bs[lc+0][r] = vb.x; Bs[lc+1][r] = vb.y;
            Bs[lc+2][r] = vb.z; Bs[lc+3][r] = vb.w;
        }
        __syncthreads();
        #pragma unroll
        for (int kk = 0; kk < 16; ++kk) {
            float a[8], b[8];
            *(float4*)&a[0] = *(const float4*)&As[kk][ty * 8];
            *(float4*)&a[4] = *(const float4*)&As[kk][ty * 8 + 4];
            *(float4*)&b[0] = *(const float4*)&Bs[kk][tx * 8];
            *(float4*)&b[4] = *(const float4*)&Bs[kk][tx * 8 + 4];
            #pragma unroll
            for (int i = 0; i < 8; ++i)
                #pragma unroll
                for (int j = 0; j < 8; ++j)
                    acc[i][j] = fmaf(a[i], b[j], acc[i][j]);
        }
        __syncthreads();
    }

    #pragma unroll
    for (int i = 0; i < 8; ++i) {
        int row = m0 + ty * 8 + i;
        #pragma unroll
        for (int j = 0; j < 8; j += 4) {
            int col = n0 + tx * 8 + j;
            float4 o;
            o.x = alpha * acc[i][j+0];
            o.y = alpha * acc[i][j+1];
            o.z = alpha * acc[i][j+2];
            o.w = alpha * acc[i][j+3];
            if (bias) {
                float4 bb = *(const float4*)(bias + col);
                o.x += bb.x; o.y += bb.y; o.z += bb.z; o.w += bb.w;
            }
            *(float4*)(C + (size_t)row * N + col) = o;
        }
    }
}

// ---------------------------------------------------------------------------
// NN GEMM: C[m,n] = sum_k A[m,k] * Bw[k,n]
// A: M x K row-major, Bw: K x N row-major. Same tiling as gemm_nt.
// ---------------------------------------------------------------------------
__global__ __launch_bounds__(256, 2)
void gemm_nn(const float* __restrict__ A, const float* __restrict__ Bw,
             float* __restrict__ C,
             int M, int N, int K,
             size_t sA, size_t sB, size_t sC)
{
    A  += sA * (size_t)blockIdx.z;
    Bw += sB * (size_t)blockIdx.z;
    C  += sC * (size_t)blockIdx.z;

    const int m0 = blockIdx.y * 128;
    const int n0 = blockIdx.x * 128;

    __shared__ float As[16][132];
    __shared__ float Bs[16][132];

    const int tid = threadIdx.x;
    const int tx = tid & 15, ty = tid >> 4;
    const int lr = tid >> 2;          // A loader: 0..63
    const int lc = (tid & 3) << 2;
    const int kb = tid >> 5;          // B loader: 0..7
    const int nb = (tid & 31) << 2;   // 0..124

    float acc[8][8];
    #pragma unroll
    for (int i = 0; i < 8; ++i)
        #pragma unroll
        for (int j = 0; j < 8; ++j) acc[i][j] = 0.f;

    for (int k0 = 0; k0 < K; k0 += 16) {
        #pragma unroll
        for (int h = 0; h < 2; ++h) {
            int r = lr + h * 64;
            float4 va = *(const float4*)(A + (size_t)(m0 + r) * K + k0 + lc);
            As[lc+0][r] = va.x; As[lc+1][r] = va.y;
            As[lc+2][r] = va.z; As[lc+3][r] = va.w;
            int kk2 = kb + h * 8;
            float4 vb = *(const float4*)(Bw + (size_t)(k0 + kk2) * N + n0 + nb);
            *(float4*)&Bs[kk2][nb] = vb;
        }
        __syncthreads();
        #pragma unroll
        for (int kk = 0; kk < 16; ++kk) {
            float a[8], b[8];
            *(float4*)&a[0] = *(const float4*)&As[kk][ty * 8];
            *(float4*)&a[4] = *(const float4*)&As[kk][ty * 8 + 4];
            *(float4*)&b[0] = *(const float4*)&Bs[kk][tx * 8];
            *(float4*)&b[4] = *(const float4*)&Bs[kk][tx * 8 + 4];
            #pragma unroll
            for (int i = 0; i < 8; ++i)
                #pragma unroll
                for (int j = 0; j < 8; ++j)
                    acc[i][j] = fmaf(a[i], b[j], acc[i][j]);
        }
        __syncthreads();
    }

    #pragma unroll
    for (int i = 0; i < 8; ++i) {
        int row = m0 + ty * 8 + i;
        #pragma unroll
        for (int j = 0; j < 8; j += 4) {
            int col = n0 + tx * 8 + j;
            float4 o;
            o.x = acc[i][j+0]; o.y = acc[i][j+1];
            o.z = acc[i][j+2]; o.w = acc[i][j+3];
            *(float4*)(C + (size_t)row * N + col) = o;
        }
    }
}

// ---------------------------------------------------------------------------
// softmax over rows of g_sc (each row = S_LEN floats), in place.
// grid = BATCH*S_LEN rows, 256 threads.
// ---------------------------------------------------------------------------
__global__ __launch_bounds__(256) void softmax_rows(float* __restrict__ sc) {
    float4* p4 = (float4*)(sc + (size_t)blockIdx.x * S_LEN);
    const int tid = threadIdx.x;
    __shared__ float red[8];

    float lmax = -1e30f;
    #pragma unroll
    for (int i = tid; i < S_LEN / 4; i += 256) {
        float4 v = p4[i];
        lmax = fmaxf(lmax, fmaxf(fmaxf(v.x, v.y), fmaxf(v.z, v.w)));
    }
    #pragma unroll
    for (int o = 16; o; o >>= 1) lmax = fmaxf(lmax, __shfl_xor_sync(~0u, lmax, o));
    if ((tid & 31) == 0) red[tid >> 5] = lmax;
    __syncthreads();
    float gmax = red[0];
    #pragma unroll
    for (int w = 1; w < 8; ++w) gmax = fmaxf(gmax, red[w]);
    __syncthreads();

    float lsum = 0.f;
    #pragma unroll
    for (int i = tid; i < S_LEN / 4; i += 256) {
        float4 v = p4[i];
        v.x = __expf(v.x - gmax); v.y = __expf(v.y - gmax);
        v.z = __expf(v.z - gmax); v.w = __expf(v.w - gmax);
        lsum += (v.x + v.y) + (v.z + v.w);
        p4[i] = v;
    }
    #pragma unroll
    for (int o = 16; o; o >>= 1) lsum += __shfl_xor_sync(~0u, lsum, o);
    if ((tid & 31) == 0) red[tid >> 5] = lsum;
    __syncthreads();
    float gsum = 0.f;
    #pragma unroll
    for (int w = 0; w < 8; ++w) gsum += red[w];
    float inv = 1.f / gsum;

    #pragma unroll
    for (int i = tid; i < S_LEN / 4; i += 256) {
        float4 v = p4[i];
        v.x *= inv; v.y *= inv; v.z *= inv; v.w *= inv;
        p4[i] = v;
    }
}

// ---------------------------------------------------------------------------
extern "C" void kernel_launch(void* const* d_in, const int* in_sizes, int n_in,
                              void* d_out, int out_size) {
    const float* x  = (const float*)d_in[0];
    const float* Wq = (const float*)d_in[1];
    const float* bq = (const float*)d_in[2];
    const float* Wk = (const float*)d_in[3];
    const float* bk = (const float*)d_in[4];
    const float* Wv = (const float*)d_in[5];
    const float* bv = (const float*)d_in[6];
    float* out = (float*)d_out;

    float *xf, *q, *k, *v, *sc;
    cudaGetSymbolAddress((void**)&xf, g_xf);
    cudaGetSymbolAddress((void**)&q,  g_q);
    cudaGetSymbolAddress((void**)&k,  g_k);
    cudaGetSymbolAddress((void**)&v,  g_v);
    cudaGetSymbolAddress((void**)&sc, g_sc);

    // 1) x (S,B,D) -> xf (B,S,D)
    transpose_x<<<MQKV, 256>>>(x, xf);

    // 2) QKV projections: (8192x1024) @ (1024x1024)^T + bias
    {
        dim3 grid(DIM / 128, MQKV / 128, 1);
        gemm_nt<<<grid, 256>>>(xf, Wq, bq, q, MQKV, DIM, DIM, 1.f, 0, 0, 0);
        gemm_nt<<<grid, 256>>>(xf, Wk, bk, k, MQKV, DIM, DIM, 1.f, 0, 0, 0);
        gemm_nt<<<grid, 256>>>(xf, Wv, bv, v, MQKV, DIM, DIM, 1.f, 0, 0, 0);
    }

    // 3) scores = (Q K^T) / sqrt(D), batched over B
    {
        dim3 grid(S_LEN / 128, S_LEN / 128, BATCH);
        gemm_nt<<<grid, 256>>>(q, k, nullptr, sc,
                               S_LEN, S_LEN, DIM, 0.03125f,
                               (size_t)S_LEN * DIM, (size_t)S_LEN * DIM,
                               (size_t)S_LEN * S_LEN);
    }

    // 4) softmax over last dim, in place
    softmax_rows<<<BATCH * S_LEN, 256>>>(sc);

    // 5) out = P @ V, batched over B; writes d_out directly ((B,S,D) flat ==
    //    reshape(weighted, x.shape))
    {
        dim3 grid(DIM / 128, S_LEN / 128, BATCH);
        gemm_nn<<<grid, 256>>>(sc, v, out,
                               S_LEN, DIM, S_LEN,
                               (size_t)S_LEN * S_LEN, (size_t)S_LEN * DIM,
                               (size_t)S_LEN * DIM);
    }
}

// round 4
// speedup vs baseline: 2.5832x; 2.5832x over previous
#include <cuda_runtime.h>
#include <cuda_bf16.h>
#include <cstdint>
#include <cstddef>

#define S_LEN 2048
#define BATCH 4
#define DIM   1024
#define MQKV  (BATCH * S_LEN)   // 8192

// ---------------------------------------------------------------------------
// scratch (static device globals; no allocation in kernel_launch)
// ---------------------------------------------------------------------------
#define DEVBF(name, n) __device__ __align__(256) __nv_bfloat16 name[n]
DEVBF(g_xh,  (size_t)MQKV * DIM);
DEVBF(g_xl,  (size_t)MQKV * DIM);
DEVBF(g_wqh, (size_t)DIM * DIM);  DEVBF(g_wql, (size_t)DIM * DIM);
DEVBF(g_wkh, (size_t)DIM * DIM);  DEVBF(g_wkl, (size_t)DIM * DIM);
DEVBF(g_wvh, (size_t)DIM * DIM);  DEVBF(g_wvl, (size_t)DIM * DIM);
DEVBF(g_qh,  (size_t)MQKV * DIM); DEVBF(g_ql,  (size_t)MQKV * DIM);
DEVBF(g_kh,  (size_t)MQKV * DIM); DEVBF(g_kl,  (size_t)MQKV * DIM);
DEVBF(g_vh,  (size_t)MQKV * DIM); DEVBF(g_vl,  (size_t)MQKV * DIM);
DEVBF(g_vth, (size_t)MQKV * DIM); DEVBF(g_vtl, (size_t)MQKV * DIM);
DEVBF(g_ph,  (size_t)BATCH * S_LEN * S_LEN);
DEVBF(g_pl,  (size_t)BATCH * S_LEN * S_LEN);
__device__ __align__(256) float g_sc[(size_t)BATCH * S_LEN * S_LEN];

// ---------------------------------------------------------------------------
// PTX helpers — all non-'a'-suffix ISA (sm_80+ features): cp.async, ldmatrix,
// mma.sync. No tcgen05 (rejected by this toolchain's compute_103 PTX target).
// ---------------------------------------------------------------------------
__device__ __forceinline__ uint32_t smem_to_u32(const void* p) {
    uint32_t a;
    asm("{ .reg .u64 t; cvta.to.shared.u64 t, %1; cvt.u32.u64 %0, t; }"
        : "=r"(a) : "l"(p));
    return a;
}
__device__ __forceinline__ void cp_async16(uint32_t s, const void* g) {
    asm volatile("cp.async.cg.shared.global [%0], [%1], 16;" :: "r"(s), "l"(g));
}
#define CP_COMMIT() asm volatile("cp.async.commit_group;" ::: "memory")
#define CP_WAIT(n)  asm volatile("cp.async.wait_group %0;" :: "n"(n) : "memory")

__device__ __forceinline__ void ldsm_x4(uint32_t* r, uint32_t addr) {
    asm volatile("ldmatrix.sync.aligned.m8n8.x4.shared.b16 {%0,%1,%2,%3}, [%4];"
        : "=r"(r[0]), "=r"(r[1]), "=r"(r[2]), "=r"(r[3]) : "r"(addr));
}
__device__ __forceinline__ void mma16816(float* c, const uint32_t* a,
                                         uint32_t b0, uint32_t b1) {
    asm volatile(
        "mma.sync.aligned.m16n8k16.row.col.f32.bf16.bf16.f32 "
        "{%0,%1,%2,%3}, {%4,%5,%6,%7}, {%8,%9}, {%0,%1,%2,%3};"
        : "+f"(c[0]), "+f"(c[1]), "+f"(c[2]), "+f"(c[3])
        : "r"(a[0]), "r"(a[1]), "r"(a[2]), "r"(a[3]), "r"(b0), "r"(b1));
}

__device__ __forceinline__ void f2pair(float v, __nv_bfloat16& h, __nv_bfloat16& l) {
    h = __float2bfloat16(v);
    l = __float2bfloat16(v - __bfloat162float(h));
}

// ---------------------------------------------------------------------------
// NT GEMM, bf16 3-term fp32 emulation, tensor cores via mma.sync.
//   C[m,n] = alpha * sum_k (Ah+Al)[m,k]*(Bh+Bl)[n,k] (+ bias[n])   [hh+hl+lh]
// CTA tile 128x128, 8 warps (2x4) of 64x32 warp tiles, K-chunk 32,
// cp.async double buffer, ldmatrix operand fetch. Batched via blockIdx.z.
// Outputs fp32 (Cf) and/or bf16 hi/lo re-split (Ch, Cl).
// ---------------------------------------------------------------------------
#define ROW_B     80                 // 32 bf16 = 64B data + 16B pad (LDSM conflict-free)
#define TILE_B    (128 * ROW_B)      // 10240 B
#define STAGE_B   (4 * TILE_B)       // Ah, Al, Bh, Bl
#define GEMM_SMEM (2 * STAGE_B)      // 81920 B

__global__ __launch_bounds__(256)
void gemm_bf3(const __nv_bfloat16* __restrict__ Ah, const __nv_bfloat16* __restrict__ Al,
              const __nv_bfloat16* __restrict__ Bh, const __nv_bfloat16* __restrict__ Bl,
              const float* __restrict__ bias,
              float* __restrict__ Cf,
              __nv_bfloat16* __restrict__ Ch, __nv_bfloat16* __restrict__ Cl,
              int M, int N, int K, float alpha,
              size_t sA, size_t sB, size_t sC)
{
    extern __shared__ __align__(16) char smem[];
    const uint32_t smem_u = smem_to_u32(smem);

    const int tid  = threadIdx.x;
    const int wid  = tid >> 5, lane = tid & 31;
    const int wm   = wid >> 2;        // 0..1 : warp row (64 rows each)
    const int wn   = wid & 3;         // 0..3 : warp col (32 cols each)
    const int m0   = blockIdx.y * 128;
    const int n0   = blockIdx.x * 128;

    Ah += sA * blockIdx.z; Al += sA * blockIdx.z;
    Bh += sB * blockIdx.z; Bl += sB * blockIdx.z;

    // ---- loader: 4 tiles x 512 16B-chunks, 2 chunks per thread per tile ----
    const int ci0 = tid;               // chunk ids: tid, tid+256
    auto load_stage = [&](int c, int s) {
        const int k0 = c * 32;
        const uint32_t st = smem_u + s * STAGE_B;
        const __nv_bfloat16* gsrc[4] = { Ah, Al, Bh, Bl };
        const int rb[4] = { m0, m0, n0, n0 };
        #pragma unroll
        for (int t = 0; t < 4; ++t) {
            #pragma unroll
            for (int h = 0; h < 2; ++h) {
                int ci  = ci0 + h * 256;
                int row = ci >> 2, col = ci & 3;
                const void* g = gsrc[t] + (size_t)(rb[t] + row) * K + k0 + col * 8;
                cp_async16(st + t * TILE_B + row * ROW_B + col * 16, g);
            }
        }
        CP_COMMIT();
    };

    float acc[4][4][4];
    #pragma unroll
    for (int i = 0; i < 4; ++i)
        #pragma unroll
        for (int j = 0; j < 4; ++j)
            #pragma unroll
            for (int e = 0; e < 4; ++e) acc[i][j][e] = 0.f;

    const int NC = K >> 5;             // K / 32
    load_stage(0, 0);

    for (int c = 0; c < NC; ++c) {
        if (c + 1 < NC) { load_stage(c + 1, (c + 1) & 1); CP_WAIT(1); }
        else            { CP_WAIT(0); }
        __syncthreads();

        const uint32_t st = smem_u + (c & 1) * STAGE_B;
        // lane-derived ldmatrix addresses
        const uint32_t aoff = (uint32_t)((wm * 64 + (lane & 15)) * ROW_B +
                                         ((lane & 16) ? 16 : 0));
        const uint32_t boff = (uint32_t)((wn * 32 + ((lane & 16) >> 1) + (lane & 7)) * ROW_B +
                                         ((lane & 8) ? 16 : 0));
        #pragma unroll
        for (int kk = 0; kk < 2; ++kk) {    // two k16 steps per chunk
            const uint32_t kb = kk * 32;    // 16 bf16 = 32 B
            uint32_t ah[4][4], al[4][4], bh[2][4], bl[2][4];
            #pragma unroll
            for (int mi = 0; mi < 4; ++mi) {
                ldsm_x4(ah[mi], st + aoff + kb + mi * (16 * ROW_B));
                ldsm_x4(al[mi], st + TILE_B + aoff + kb + mi * (16 * ROW_B));
            }
            ldsm_x4(bh[0], st + 2 * TILE_B + boff + kb);
            ldsm_x4(bh[1], st + 2 * TILE_B + boff + kb + 16 * ROW_B);
            ldsm_x4(bl[0], st + 3 * TILE_B + boff + kb);
            ldsm_x4(bl[1], st + 3 * TILE_B + boff + kb + 16 * ROW_B);

            #pragma unroll
            for (int mi = 0; mi < 4; ++mi)
                #pragma unroll
                for (int nf = 0; nf < 4; ++nf) {
                    const int hsel = nf >> 1, p = (nf & 1) * 2;
                    mma16816(acc[mi][nf], ah[mi], bh[hsel][p], bh[hsel][p + 1]); // hh
                    mma16816(acc[mi][nf], ah[mi], bl[hsel][p], bl[hsel][p + 1]); // hl
                    mma16816(acc[mi][nf], al[mi], bh[hsel][p], bh[hsel][p + 1]); // lh
                }
        }
        __syncthreads();
    }

    // ---- epilogue ----
    const int r0 = lane >> 2;
    const int c0l = (lane & 3) * 2;
    #pragma unroll
    for (int mi = 0; mi < 4; ++mi) {
        #pragma unroll
        for (int nf = 0; nf < 4; ++nf) {
            const int col  = n0 + wn * 32 + nf * 8 + c0l;
            const int rowA = m0 + wm * 64 + mi * 16 + r0;
            float b0 = 0.f, b1 = 0.f;
            if (bias) { b0 = bias[col]; b1 = bias[col + 1]; }
            float v0 = fmaf(alpha, acc[mi][nf][0], b0);
            float v1 = fmaf(alpha, acc[mi][nf][1], b1);
            float v2 = fmaf(alpha, acc[mi][nf][2], b0);
            float v3 = fmaf(alpha, acc[mi][nf][3], b1);
            if (Cf) {
                float* p0 = Cf + sC * blockIdx.z + (size_t)rowA * N + col;
                *(float2*)p0                     = make_float2(v0, v1);
                *(float2*)(p0 + (size_t)8 * N)   = make_float2(v2, v3);
            }
            if (Ch) {
                size_t o0 = sC * blockIdx.z + (size_t)rowA * N + col;
                __nv_bfloat16 h0, l0, h1, l1;
                f2pair(v0, h0, l0); f2pair(v1, h1, l1);
                *(__nv_bfloat162*)(Ch + o0) = __nv_bfloat162(h0, h1);
                *(__nv_bfloat162*)(Cl + o0) = __nv_bfloat162(l0, l1);
                f2pair(v2, h0, l0); f2pair(v3, h1, l1);
                *(__nv_bfloat162*)(Ch + o0 + (size_t)8 * N) = __nv_bfloat162(h0, h1);
                *(__nv_bfloat162*)(Cl + o0 + (size_t)8 * N) = __nv_bfloat162(l0, l1);
            }
        }
    }
}

// ---------------------------------------------------------------------------
// x (S,B,D) fp32 -> xf (B,S,D) bf16 hi/lo
// ---------------------------------------------------------------------------
__global__ __launch_bounds__(256) void conv_x(const float* __restrict__ x,
                                              __nv_bfloat16* __restrict__ xh,
                                              __nv_bfloat16* __restrict__ xl) {
    int bs = blockIdx.x;
    int b = bs / S_LEN, s = bs % S_LEN;
    float4 v = ((const float4*)(x + ((size_t)s * BATCH + b) * DIM))[threadIdx.x];
    size_t o = (size_t)bs * DIM + (size_t)threadIdx.x * 4;
    __nv_bfloat16 h0,l0,h1,l1,h2,l2,h3,l3;
    f2pair(v.x, h0, l0); f2pair(v.y, h1, l1);
    f2pair(v.z, h2, l2); f2pair(v.w, h3, l3);
    ((__nv_bfloat162*)(xh + o))[0] = __nv_bfloat162(h0, h1);
    ((__nv_bfloat162*)(xh + o))[1] = __nv_bfloat162(h2, h3);
    ((__nv_bfloat162*)(xl + o))[0] = __nv_bfloat162(l0, l1);
    ((__nv_bfloat162*)(xl + o))[1] = __nv_bfloat162(l2, l3);
}

// fp32 array -> bf16 hi/lo (vectorized)
__global__ __launch_bounds__(256) void conv_pair(const float* __restrict__ X,
                                                 __nv_bfloat16* __restrict__ H,
                                                 __nv_bfloat16* __restrict__ L,
                                                 int n4) {
    int i = blockIdx.x * 256 + threadIdx.x;
    if (i >= n4) return;
    float4 v = ((const float4*)X)[i];
    size_t o = (size_t)i * 4;
    __nv_bfloat16 h0,l0,h1,l1,h2,l2,h3,l3;
    f2pair(v.x, h0, l0); f2pair(v.y, h1, l1);
    f2pair(v.z, h2, l2); f2pair(v.w, h3, l3);
    ((__nv_bfloat162*)(H + o))[0] = __nv_bfloat162(h0, h1);
    ((__nv_bfloat162*)(H + o))[1] = __nv_bfloat162(h2, h3);
    ((__nv_bfloat162*)(L + o))[0] = __nv_bfloat162(l0, l1);
    ((__nv_bfloat162*)(L + o))[1] = __nv_bfloat162(l2, l3);
}

// bf16 RxC -> CxR transpose (per batch z)
__global__ __launch_bounds__(256) void transpose_bf16(const __nv_bfloat16* __restrict__ in,
                                                      __nv_bfloat16* __restrict__ out,
                                                      int R, int C) {
    __shared__ __nv_bfloat16 t[32][33];
    in  += (size_t)blockIdx.z * R * C;
    out += (size_t)blockIdx.z * R * C;
    int c0 = blockIdx.x * 32, r0 = blockIdx.y * 32;
    #pragma unroll
    for (int i = threadIdx.y; i < 32; i += 8)
        t[i][threadIdx.x] = in[(size_t)(r0 + i) * C + c0 + threadIdx.x];
    __syncthreads();
    #pragma unroll
    for (int i = threadIdx.y; i < 32; i += 8)
        out[(size_t)(c0 + i) * R + r0 + threadIdx.x] = t[threadIdx.x][i];
}

// softmax over rows of sc (fp32, len S_LEN) -> bf16 hi/lo probs
__global__ __launch_bounds__(256) void softmax_conv(const float* __restrict__ sc,
                                                    __nv_bfloat16* __restrict__ ph,
                                                    __nv_bfloat16* __restrict__ pl) {
    const int tid = threadIdx.x;
    const float4* p4 = (const float4*)(sc + (size_t)blockIdx.x * S_LEN);
    __shared__ float red[8];

    float4 a = p4[tid], b = p4[tid + 256];
    float lmax = fmaxf(fmaxf(fmaxf(a.x, a.y), fmaxf(a.z, a.w)),
                       fmaxf(fmaxf(b.x, b.y), fmaxf(b.z, b.w)));
    #pragma unroll
    for (int o = 16; o; o >>= 1) lmax = fmaxf(lmax, __shfl_xor_sync(~0u, lmax, o));
    if ((tid & 31) == 0) red[tid >> 5] = lmax;
    __syncthreads();
    float gmax = red[0];
    #pragma unroll
    for (int w = 1; w < 8; ++w) gmax = fmaxf(gmax, red[w]);
    __syncthreads();

    float e[8];
    e[0] = __expf(a.x - gmax); e[1] = __expf(a.y - gmax);
    e[2] = __expf(a.z - gmax); e[3] = __expf(a.w - gmax);
    e[4] = __expf(b.x - gmax); e[5] = __expf(b.y - gmax);
    e[6] = __expf(b.z - gmax); e[7] = __expf(b.w - gmax);
    float lsum = ((e[0]+e[1]) + (e[2]+e[3])) + ((e[4]+e[5]) + (e[6]+e[7]));
    #pragma unroll
    for (int o = 16; o; o >>= 1) lsum += __shfl_xor_sync(~0u, lsum, o);
    if ((tid & 31) == 0) red[tid >> 5] = lsum;
    __syncthreads();
    float gsum = 0.f;
    #pragma unroll
    for (int w = 0; w < 8; ++w) gsum += red[w];
    float inv = 1.f / gsum;

    size_t o0 = (size_t)blockIdx.x * S_LEN + (size_t)tid * 4;
    #pragma unroll
    for (int half = 0; half < 2; ++half) {
        size_t o = o0 + half * 1024;
        __nv_bfloat16 h0,l0,h1,l1,h2,l2,h3,l3;
        f2pair(e[half*4+0] * inv, h0, l0);
        f2pair(e[half*4+1] * inv, h1, l1);
        f2pair(e[half*4+2] * inv, h2, l2);
        f2pair(e[half*4+3] * inv, h3, l3);
        ((__nv_bfloat162*)(ph + o))[0] = __nv_bfloat162(h0, h1);
        ((__nv_bfloat162*)(ph + o))[1] = __nv_bfloat162(h2, h3);
        ((__nv_bfloat162*)(pl + o))[0] = __nv_bfloat162(l0, l1);
        ((__nv_bfloat162*)(pl + o))[1] = __nv_bfloat162(l2, l3);
    }
}

// ---------------------------------------------------------------------------
extern "C" void kernel_launch(void* const* d_in, const int* in_sizes, int n_in,
                              void* d_out, int out_size) {
    const float* x  = (const float*)d_in[0];
    const float* Wq = (const float*)d_in[1];
    const float* bq = (const float*)d_in[2];
    const float* Wk = (const float*)d_in[3];
    const float* bk = (const float*)d_in[4];
    const float* Wv = (const float*)d_in[5];
    const float* bv = (const float*)d_in[6];
    float* out = (float*)d_out;

    cudaFuncSetAttribute(gemm_bf3, cudaFuncAttributeMaxDynamicSharedMemorySize,
                         GEMM_SMEM);

    __nv_bfloat16 *xh, *xl, *wqh, *wql, *wkh, *wkl, *wvh, *wvl;
    __nv_bfloat16 *qh, *ql, *kh, *kl, *vh, *vl, *vth, *vtl, *ph, *pl;
    float* sc;
    cudaGetSymbolAddress((void**)&xh, g_xh);   cudaGetSymbolAddress((void**)&xl, g_xl);
    cudaGetSymbolAddress((void**)&wqh, g_wqh); cudaGetSymbolAddress((void**)&wql, g_wql);
    cudaGetSymbolAddress((void**)&wkh, g_wkh); cudaGetSymbolAddress((void**)&wkl, g_wkl);
    cudaGetSymbolAddress((void**)&wvh, g_wvh); cudaGetSymbolAddress((void**)&wvl, g_wvl);
    cudaGetSymbolAddress((void**)&qh, g_qh);   cudaGetSymbolAddress((void**)&ql, g_ql);
    cudaGetSymbolAddress((void**)&kh, g_kh);   cudaGetSymbolAddress((void**)&kl, g_kl);
    cudaGetSymbolAddress((void**)&vh, g_vh);   cudaGetSymbolAddress((void**)&vl, g_vl);
    cudaGetSymbolAddress((void**)&vth, g_vth); cudaGetSymbolAddress((void**)&vtl, g_vtl);
    cudaGetSymbolAddress((void**)&ph, g_ph);   cudaGetSymbolAddress((void**)&pl, g_pl);
    cudaGetSymbolAddress((void**)&sc, g_sc);

    // 1) input conversions
    conv_x<<<MQKV, 256>>>(x, xh, xl);
    conv_pair<<<DIM * DIM / 4 / 256, 256>>>(Wq, wqh, wql, DIM * DIM / 4);
    conv_pair<<<DIM * DIM / 4 / 256, 256>>>(Wk, wkh, wkl, DIM * DIM / 4);
    conv_pair<<<DIM * DIM / 4 / 256, 256>>>(Wv, wvh, wvl, DIM * DIM / 4);

    // 2) QKV projections -> bf16 pairs directly (fused re-split epilogue)
    {
        dim3 grid(DIM / 128, MQKV / 128, 1);
        gemm_bf3<<<grid, 256, GEMM_SMEM>>>(xh, xl, wqh, wql, bq, nullptr, qh, ql,
                                           MQKV, DIM, DIM, 1.f, 0, 0, 0);
        gemm_bf3<<<grid, 256, GEMM_SMEM>>>(xh, xl, wkh, wkl, bk, nullptr, kh, kl,
                                           MQKV, DIM, DIM, 1.f, 0, 0, 0);
        gemm_bf3<<<grid, 256, GEMM_SMEM>>>(xh, xl, wvh, wvl, bv, nullptr, vh, vl,
                                           MQKV, DIM, DIM, 1.f, 0, 0, 0);
    }

    // 3) V -> V^T (per batch, [S,D] -> [D,S]) for K-major PV operand
    {
        dim3 grid(DIM / 32, S_LEN / 32, BATCH);
        dim3 blk(32, 8);
        transpose_bf16<<<grid, blk>>>(vh, vth, S_LEN, DIM);
        transpose_bf16<<<grid, blk>>>(vl, vtl, S_LEN, DIM);
    }

    // 4) scores = Q K^T / sqrt(D)  (fp32 out)
    {
        dim3 grid(S_LEN / 128, S_LEN / 128, BATCH);
        gemm_bf3<<<grid, 256, GEMM_SMEM>>>(qh, ql, kh, kl, nullptr, sc, nullptr, nullptr,
                                           S_LEN, S_LEN, DIM, 0.03125f,
                                           (size_t)S_LEN * DIM, (size_t)S_LEN * DIM,
                                           (size_t)S_LEN * S_LEN);
    }

    // 5) softmax -> bf16 prob pairs
    softmax_conv<<<BATCH * S_LEN, 256>>>(sc, ph, pl);

    // 6) out = P V  (fp32 straight into d_out; (B,S,D) flat == reshape)
    {
        dim3 grid(DIM / 128, S_LEN / 128, BATCH);
        gemm_bf3<<<grid, 256, GEMM_SMEM>>>(ph, pl, vth, vtl, nullptr, out, nullptr, nullptr,
                                           S_LEN, DIM, S_LEN, 1.f,
                                           (size_t)S_LEN * S_LEN, (size_t)S_LEN * DIM,
                                           (size_t)S_LEN * DIM);
    }
}